// round 1
// baseline (speedup 1.0000x reference)
#include <cuda_runtime.h>
#include <cuda_bf16.h>

// Problem constants
#define Bc 2
#define Nc 96
#define NNc 9216            // Nc*Nc
#define Dc 64
#define Hc 4
#define DKc 16
#define ROWS_TOTAL 18432    // Bc*NNc

// Scratch (device globals; allocation-free per harness rules)
// g_proj layout: [proj(4)][b(2)][h(4)][i(9216)][d(16)]
__device__ float g_proj[4u * Bc * Hc * NNc * DKc];   // 18.9 MB
__device__ float g_attout[(size_t)ROWS_TOTAL * Dc];  // 4.7 MB

// ---------------------------------------------------------------------------
// Kernel A: fused 4-way projection.  out256[row][p] = state[row][:] @ W_p^T + b
// Block: 256 threads, 32 rows per block.  All 4 weight matrices in smem.
// ---------------------------------------------------------------------------
#define A_WS_STRIDE 260   // padded stride for w_s[k][pcol]

__global__ void __launch_bounds__(256)
proj_kernel(const float* __restrict__ state,
            const float* __restrict__ w_lk, const float* __restrict__ b_lk,
            const float* __restrict__ w_rk, const float* __restrict__ b_rk,
            const float* __restrict__ w_lv, const float* __restrict__ b_lv,
            const float* __restrict__ w_rv, const float* __restrict__ b_rv)
{
    extern __shared__ __align__(16) float smem[];
    float* w_s   = smem;                       // 64 * 260 = 16640 floats
    float* st_s  = smem + 64 * A_WS_STRIDE;    // 32 * 64   = 2048 floats
    float* bias_s = st_s + 32 * 64;            // 256 floats

    const int tid = threadIdx.x;
    const int rowBase = blockIdx.x * 32;

    // Load weights transposed: w_s[k][proj*64 + p] = W_proj[p][k]
#pragma unroll
    for (int proj = 0; proj < 4; ++proj) {
        const float* W = (proj == 0) ? w_lk : (proj == 1) ? w_rk
                        : (proj == 2) ? w_lv : w_rv;
        for (int idx = tid; idx < 4096; idx += 256) {
            int p = idx >> 6, k = idx & 63;
            w_s[k * A_WS_STRIDE + proj * 64 + p] = W[idx];
        }
    }
    {
        const float* bsrc = (tid < 64) ? b_lk : (tid < 128) ? b_rk
                           : (tid < 192) ? b_lv : b_rv;
        bias_s[tid] = bsrc[tid & 63];
    }
    // Load state tile (contiguous 32*64 floats)
    {
        const float4* src = (const float4*)(state + (size_t)rowBase * 64);
        float4* dst = (float4*)st_s;
        for (int i = tid; i < 512; i += 256) dst[i] = src[i];
    }
    __syncthreads();

    const int pg = (tid & 63) * 4;   // output column group (0..252, step 4)
    const int r0 = (tid >> 6) * 8;   // row group within tile

    float acc[8][4];
#pragma unroll
    for (int i = 0; i < 8; ++i)
#pragma unroll
        for (int j = 0; j < 4; ++j) acc[i][j] = 0.f;

#pragma unroll 8
    for (int k = 0; k < 64; ++k) {
        float4 wv = *(const float4*)&w_s[k * A_WS_STRIDE + pg];
#pragma unroll
        for (int i = 0; i < 8; ++i) {
            float s = st_s[(r0 + i) * 64 + k];
            acc[i][0] += s * wv.x;
            acc[i][1] += s * wv.y;
            acc[i][2] += s * wv.z;
            acc[i][3] += s * wv.w;
        }
    }

    const float4 bv = *(const float4*)&bias_s[pg];
    const int proj = pg >> 6;
    const int h    = (pg >> 4) & 3;
    const int d    = pg & 15;

#pragma unroll
    for (int i = 0; i < 8; ++i) {
        int row = rowBase + r0 + i;
        int b   = row / NNc;
        int idx = row - b * NNc;
        float4 v;
        v.x = acc[i][0] + bv.x;
        v.y = acc[i][1] + bv.y;
        v.z = acc[i][2] + bv.z;
        v.w = acc[i][3] + bv.w;
        size_t off = ((size_t)((proj * Bc + b) * Hc + h) * NNc + idx) * DKc + d;
        *(float4*)&g_proj[off] = v;
    }
}

// ---------------------------------------------------------------------------
// Kernel B: scores + softmax(a) + triple-product contraction.
// Block per (b, h, x-tile of 2).  y processed in halves of 48 to keep the
// score tile in smem (61.8 KB total -> 3 blocks/SM, single wave of 384).
// ---------------------------------------------------------------------------
#define TXc 2
#define YHc 48

__global__ void __launch_bounds__(384, 3)
attn_kernel()
{
    extern __shared__ __align__(16) float smem[];
    float* lk_s = smem;                 // TX * 96 * 16 = 3072
    float* lv_s = smem + 3072;          // 3072
    float* sc   = smem + 6144;          // TX * 96 * 48 = 9216
    float* linv = smem + 15360;         // 96

    const int tid = threadIdx.x;
    const int xt = blockIdx.x % 48;
    const int bh = blockIdx.x / 48;
    const int h  = bh % Hc;
    const int b  = bh / Hc;
    const int x0 = xt * TXc;

    const int slab = NNc * DKc;  // 147456
    const float* lkbase = g_proj + (size_t)((0 * Bc + b) * Hc + h) * slab;
    const float* rkbase = g_proj + (size_t)((1 * Bc + b) * Hc + h) * slab;
    const float* lvbase = g_proj + (size_t)((2 * Bc + b) * Hc + h) * slab;
    const float* rvbase = g_proj + (size_t)((3 * Bc + b) * Hc + h) * slab;

    // Phase 1: load lk / lv for the two x's (each 1536 floats = 384 float4)
    for (int i = tid; i < TXc * 384; i += 384) {
        int tx = i / 384;
        int j  = i - tx * 384;
        ((float4*)lk_s)[tx * 384 + j] =
            ((const float4*)(lkbase + (size_t)(x0 + tx) * 1536))[j];
        ((float4*)lv_s)[tx * 384 + j] =
            ((const float4*)(lvbase + (size_t)(x0 + tx) * 1536))[j];
    }
    __syncthreads();

    for (int yh = 0; yh < 96; yh += YHc) {
        // ---- Phase 2: scores[tx][a][yl] = (lk_x[a,:] . rk[a,y,:]) * 0.25
        for (int idx = tid; idx < 96 * YHc; idx += 384) {
            int a  = idx / YHc;
            int yl = idx - a * YHc;
            int y  = yh + yl;
            const float4* rp = (const float4*)(rkbase + (size_t)(a * 96 + y) * 16);
            float4 r0v = rp[0], r1v = rp[1], r2v = rp[2], r3v = rp[3];
#pragma unroll
            for (int tx = 0; tx < TXc; ++tx) {
                const float4* lp = (const float4*)(lk_s + tx * 1536 + a * 16);
                float4 l0 = lp[0], l1 = lp[1], l2 = lp[2], l3 = lp[3];
                float s0 = l0.x * r0v.x + l0.y * r0v.y + l0.z * r0v.z + l0.w * r0v.w;
                float s1 = l1.x * r1v.x + l1.y * r1v.y + l1.z * r1v.z + l1.w * r1v.w;
                float s2 = l2.x * r2v.x + l2.y * r2v.y + l2.z * r2v.z + l2.w * r2v.w;
                float s3 = l3.x * r3v.x + l3.y * r3v.y + l3.z * r3v.z + l3.w * r3v.w;
                sc[tx * 96 * YHc + a * YHc + yl] = (s0 + s1 + s2 + s3) * 0.25f;
            }
        }
        __syncthreads();

        // ---- Softmax over a (unnormalized exp; keep 1/sum)
        if (tid < 96) {
            int tx = tid / YHc;
            int yl = tid - tx * YHc;
            float* col = sc + tx * 96 * YHc + yl;
            float m = -1e30f;
#pragma unroll 4
            for (int a = 0; a < 96; ++a) m = fmaxf(m, col[a * YHc]);
            float l = 0.f;
#pragma unroll 4
            for (int a = 0; a < 96; ++a) {
                float e = __expf(col[a * YHc] - m);
                col[a * YHc] = e;
                l += e;
            }
            linv[tid] = 1.f / l;
        }
        __syncthreads();

        // ---- Phase 3: out[tx][y][d] = (1/l) * sum_a e[a,y]*lv[a,d]*rv[a,y,d]
        if (tid < 192) {
            int yl = tid >> 2;
            int dq = tid & 3;
            int y  = yh + yl;
            float4 acc0 = {0.f, 0.f, 0.f, 0.f};
            float4 acc1 = {0.f, 0.f, 0.f, 0.f};
#pragma unroll 4
            for (int a = 0; a < 96; ++a) {
                float4 rv = *(const float4*)(rvbase + (size_t)(a * 96 + y) * 16 + dq * 4);
                float w0 = sc[0 * 96 * YHc + a * YHc + yl];
                float w1 = sc[1 * 96 * YHc + a * YHc + yl];
                float4 v0 = *(const float4*)(lv_s + a * 16 + dq * 4);
                float4 v1 = *(const float4*)(lv_s + 1536 + a * 16 + dq * 4);
                acc0.x += w0 * (v0.x * rv.x);
                acc0.y += w0 * (v0.y * rv.y);
                acc0.z += w0 * (v0.z * rv.z);
                acc0.w += w0 * (v0.w * rv.w);
                acc1.x += w1 * (v1.x * rv.x);
                acc1.y += w1 * (v1.y * rv.y);
                acc1.z += w1 * (v1.z * rv.z);
                acc1.w += w1 * (v1.w * rv.w);
            }
            float s0 = linv[yl];
            float s1 = linv[YHc + yl];
            acc0.x *= s0; acc0.y *= s0; acc0.z *= s0; acc0.w *= s0;
            acc1.x *= s1; acc1.y *= s1; acc1.z *= s1; acc1.w *= s1;
            size_t row0 = (size_t)b * NNc + (size_t)(x0 + 0) * 96 + y;
            size_t row1 = (size_t)b * NNc + (size_t)(x0 + 1) * 96 + y;
            *(float4*)&g_attout[row0 * 64 + h * 16 + dq * 4] = acc0;
            *(float4*)&g_attout[row1 * 64 + h * 16 + dq * 4] = acc1;
        }
        __syncthreads();
    }
}

// ---------------------------------------------------------------------------
// Kernel C: output projection.  out[i][p] = attout[i][:] @ w_out^T + b_out
// Block: 256 threads, 64 rows per block.
// ---------------------------------------------------------------------------
#define C_WS_STRIDE 68

__global__ void __launch_bounds__(256)
out_kernel(const float* __restrict__ w_out, const float* __restrict__ b_out,
           float* __restrict__ out)
{
    __shared__ __align__(16) float w_s[64 * C_WS_STRIDE];
    __shared__ __align__(16) float st_s[64 * 64];
    __shared__ float bias_s[64];

    const int tid = threadIdx.x;
    const int rowBase = blockIdx.x * 64;

    for (int idx = tid; idx < 4096; idx += 256) {
        int p = idx >> 6, k = idx & 63;
        w_s[k * C_WS_STRIDE + p] = w_out[idx];
    }
    if (tid < 64) bias_s[tid] = b_out[tid];
    {
        const float4* src = (const float4*)(g_attout + (size_t)rowBase * 64);
        float4* dst = (float4*)st_s;
        for (int i = tid; i < 1024; i += 256) dst[i] = src[i];
    }
    __syncthreads();

    const int p0 = (tid & 15) * 4;
    const int r0 = (tid >> 4) * 4;

    float acc[4][4];
#pragma unroll
    for (int i = 0; i < 4; ++i)
#pragma unroll
        for (int j = 0; j < 4; ++j) acc[i][j] = 0.f;

#pragma unroll 8
    for (int k = 0; k < 64; ++k) {
        float4 wv = *(const float4*)&w_s[k * C_WS_STRIDE + p0];
#pragma unroll
        for (int i = 0; i < 4; ++i) {
            float s = st_s[(r0 + i) * 64 + k];
            acc[i][0] += s * wv.x;
            acc[i][1] += s * wv.y;
            acc[i][2] += s * wv.z;
            acc[i][3] += s * wv.w;
        }
    }

    const float4 bv = *(const float4*)&bias_s[p0];
#pragma unroll
    for (int i = 0; i < 4; ++i) {
        int row = rowBase + r0 + i;
        float4 v;
        v.x = acc[i][0] + bv.x;
        v.y = acc[i][1] + bv.y;
        v.z = acc[i][2] + bv.z;
        v.w = acc[i][3] + bv.w;
        *(float4*)&out[(size_t)row * 64 + p0] = v;
    }
}

// ---------------------------------------------------------------------------
extern "C" void kernel_launch(void* const* d_in, const int* in_sizes, int n_in,
                              void* d_out, int out_size)
{
    const float* state = (const float*)d_in[0];
    const float* w_lk = (const float*)d_in[1];
    const float* b_lk = (const float*)d_in[2];
    const float* w_rk = (const float*)d_in[3];
    const float* b_rk = (const float*)d_in[4];
    const float* w_lv = (const float*)d_in[5];
    const float* b_lv = (const float*)d_in[6];
    const float* w_rv = (const float*)d_in[7];
    const float* b_rv = (const float*)d_in[8];
    const float* w_out = (const float*)d_in[9];
    const float* b_out = (const float*)d_in[10];
    float* out = (float*)d_out;

    static bool attr_done = false;
    if (!attr_done) {
        cudaFuncSetAttribute(proj_kernel,
                             cudaFuncAttributeMaxDynamicSharedMemorySize,
                             (64 * A_WS_STRIDE + 32 * 64 + 256) * 4);
        cudaFuncSetAttribute(attn_kernel,
                             cudaFuncAttributeMaxDynamicSharedMemorySize,
                             15456 * 4);
        attr_done = true;
    }

    int smemA = (64 * A_WS_STRIDE + 32 * 64 + 256) * 4;  // 75776 B
    proj_kernel<<<ROWS_TOTAL / 32, 256, smemA>>>(
        state, w_lk, b_lk, w_rk, b_rk, w_lv, b_lv, w_rv, b_rv);

    int smemB = 15456 * 4;  // 61824 B
    attn_kernel<<<Bc * Hc * (Nc / TXc), 384, smemB>>>();

    out_kernel<<<ROWS_TOTAL / 64, 256>>>(w_out, b_out, out);
}